// round 2
// baseline (speedup 1.0000x reference)
#include <cuda_runtime.h>
#include <cuda_bf16.h>
#include <limits.h>

#define B_DIM 32
#define C_DIM 8
#define H_DIM 512
#define W_DIM 512
#define N_IMG (B_DIM * C_DIM)          // 256
#define IMG_ELEMS (H_DIM * W_DIM)      // 262144
#define IMG_F4 (IMG_ELEMS / 4)         // 65536 float4 per image
#define CHUNKS 8                        // blocks per image
#define THREADS 256
#define GRID_BLOCKS (CHUNKS * N_IMG)    // 2048
#define F4_PER_THREAD (IMG_F4 / (CHUNKS * THREADS))  // 32

// Per-(image, chunk) partials: {xmin, ymin, xmax, ymax}. Fully overwritten
// every launch (no init kernel needed).
__device__ int4 g_part[N_IMG * CHUNKS];
// Grid ticket counter. Starts at 0 (static init); the last block resets it
// to 0 so graph replays see a clean state deterministically.
__device__ unsigned int g_counter = 0;

__global__ __launch_bounds__(THREADS) void bb_fused_kernel(
    const float* __restrict__ mask, float* __restrict__ out) {
    const int img   = blockIdx.y;              // 0..255
    const int chunk = blockIdx.x;              // 0..7
    const int tid   = threadIdx.x;

    const float4* __restrict__ img_f4 =
        reinterpret_cast<const float4*>(mask) + (size_t)img * IMG_F4;

    int xmin = INT_MAX, ymin = INT_MAX;
    int xmax = 0,       ymax = 0;

    const int base = chunk * (THREADS * F4_PER_THREAD);

#pragma unroll 8
    for (int k = 0; k < F4_PER_THREAD; k++) {
        const int idx = base + k * THREADS + tid;   // float4 index within image
        const float4 v = __ldcs(&img_f4[idx]);      // streaming: read-once data

        const int h1 = (idx >> 7) + 1;              // row + 1 (128 f4 per row)
        const int w0 = ((idx & 127) << 2) + 1;      // col of lane 0, +1

        const bool a = v.x >= 0.5f;
        const bool b = v.y >= 0.5f;
        const bool c = v.z >= 0.5f;
        const bool d = v.w >= 0.5f;
        const bool any = a | b | c | d;
        const bool all = a & b & c & d;

        // y contribution: all 4 lanes share the same row.
        //   min over lanes of (set ? h1 : 0) = all ? h1 : 0
        //   max over lanes of (set ? h1 : 0) = any ? h1 : 0
        ymin = min(ymin, all ? h1 : 0);
        ymax = max(ymax, any ? h1 : 0);

        // x contribution: lane values are w0, w0+1, w0+2, w0+3.
        //   min = all ? w0 : 0 (any unset lane contributes a 0)
        //   max = any ? (w0 + highest set lane) : 0
        const int hi = d ? 3 : (c ? 2 : (b ? 1 : 0));
        xmin = min(xmin, all ? w0 : 0);
        xmax = max(xmax, any ? (w0 + hi) : 0);
    }

    // Warp reduce (redux.sync)
    xmin = __reduce_min_sync(0xFFFFFFFFu, xmin);
    xmax = __reduce_max_sync(0xFFFFFFFFu, xmax);
    ymin = __reduce_min_sync(0xFFFFFFFFu, ymin);
    ymax = __reduce_max_sync(0xFFFFFFFFu, ymax);

    __shared__ int s_xmin[8], s_xmax[8], s_ymin[8], s_ymax[8];
    const int wid = tid >> 5;
    const int lid = tid & 31;
    if (lid == 0) {
        s_xmin[wid] = xmin; s_xmax[wid] = xmax;
        s_ymin[wid] = ymin; s_ymax[wid] = ymax;
    }
    __syncthreads();

    __shared__ bool s_is_last;
    if (tid == 0) {
        int bxmin = s_xmin[0], bxmax = s_xmax[0];
        int bymin = s_ymin[0], bymax = s_ymax[0];
#pragma unroll
        for (int w = 1; w < 8; w++) {
            bxmin = min(bxmin, s_xmin[w]); bxmax = max(bxmax, s_xmax[w]);
            bymin = min(bymin, s_ymin[w]); bymax = max(bymax, s_ymax[w]);
        }
        g_part[img * CHUNKS + chunk] = make_int4(bxmin, bymin, bxmax, bymax);
        __threadfence();
        const unsigned int ticket = atomicAdd(&g_counter, 1u);
        s_is_last = (ticket == GRID_BLOCKS - 1);
    }
    __syncthreads();

    if (!s_is_last) return;

    // ---- Last block: final reduce of 2048 partials + write outputs ----
    // Thread i handles image i (256 threads, 256 images).
    {
        const int i = tid;
        int fxmin = INT_MAX, fymin = INT_MAX, fxmax = 0, fymax = 0;
#pragma unroll
        for (int cch = 0; cch < CHUNKS; cch++) {
            const int4 p = __ldcg(&g_part[i * CHUNKS + cch]);
            fxmin = min(fxmin, p.x); fymin = min(fymin, p.y);
            fxmax = max(fxmax, p.z); fymax = max(fymax, p.w);
        }

        const float xminf = (float)fxmin;
        const float yminf = (float)fymin;
        const float xmaxf = (float)fxmax;
        const float ymaxf = (float)fymax;

        // Output layout (concatenated flattened tuple, all float32):
        //   [0,   256)  object_found           [B, C, 1]
        //   [256, 1280) bounding_boxes_scaled  [B, C, 4]  (x_min,y_min,x_max,y_max)
        //   [1280,2304) bounding_boxes         [B, C, 4]  (scaled * 2)
        out[i] = ((ymaxf > yminf) && (xmaxf > xminf)) ? 1.0f : 0.0f;

        float* bb = out + 256 + i * 4;
        bb[0] = xminf; bb[1] = yminf; bb[2] = xmaxf; bb[3] = ymaxf;

        float* bb2 = out + 1280 + i * 4;
        bb2[0] = xminf * 2.0f; bb2[1] = yminf * 2.0f;
        bb2[2] = xmaxf * 2.0f; bb2[3] = ymaxf * 2.0f;

        // Reset ticket counter for the next graph replay.
        if (tid == 0) g_counter = 0u;
    }
}

extern "C" void kernel_launch(void* const* d_in, const int* in_sizes, int n_in,
                              void* d_out, int out_size) {
    const float* mask = (const float*)d_in[0];
    float* out = (float*)d_out;

    dim3 grid(CHUNKS, N_IMG);
    bb_fused_kernel<<<grid, THREADS>>>(mask, out);
}

// round 3
// speedup vs baseline: 1.0683x; 1.0683x over previous
#include <cuda_runtime.h>
#include <cuda_bf16.h>
#include <limits.h>

#define B_DIM 32
#define C_DIM 8
#define H_DIM 512
#define W_DIM 512
#define N_IMG (B_DIM * C_DIM)          // 256
#define IMG_ELEMS (H_DIM * W_DIM)      // 262144
#define IMG_F4 (IMG_ELEMS / 4)         // 65536 float4 per image
#define CHUNKS 4                        // blocks per image
#define THREADS 256
#define GRID_BLOCKS (CHUNKS * N_IMG)    // 1024
#define F4_PER_THREAD (IMG_F4 / (CHUNKS * THREADS))  // 64

// Per-(image, chunk) partials: {xmin, ymin, xmax, ymax}. Fully overwritten
// every launch (no init kernel needed).
__device__ int4 g_part[N_IMG * CHUNKS];
// Grid ticket counter. Starts at 0 (static init); the last block resets it
// to 0 so graph replays see a clean state deterministically.
__device__ unsigned int g_counter = 0;

__device__ __forceinline__ void process_f4(const float4 v, const int idx,
                                           int& xmin, int& ymin,
                                           int& xmax, int& ymax) {
    const int h1 = (idx >> 7) + 1;              // row + 1 (128 f4 per row)
    const int w0 = ((idx & 127) << 2) + 1;      // col of lane 0, +1

    const bool a = v.x >= 0.5f;
    const bool b = v.y >= 0.5f;
    const bool c = v.z >= 0.5f;
    const bool d = v.w >= 0.5f;
    const bool any = a | b | c | d;
    const bool all = a & b & c & d;

    // y: all 4 lanes share the row. min = all?h1:0, max = any?h1:0
    ymin = min(ymin, all ? h1 : 0);
    ymax = max(ymax, any ? h1 : 0);

    // x: lane values w0..w0+3. min = all?w0:0 (any unset lane gives 0),
    // max = any ? (w0 + highest set lane) : 0
    const int hi = d ? 3 : (c ? 2 : (b ? 1 : 0));
    xmin = min(xmin, all ? w0 : 0);
    xmax = max(xmax, any ? (w0 + hi) : 0);
}

__global__ __launch_bounds__(THREADS, 7) void bb_fused_kernel(
    const float* __restrict__ mask, float* __restrict__ out) {
    const int img   = blockIdx.y;              // 0..255
    const int chunk = blockIdx.x;              // 0..3
    const int tid   = threadIdx.x;

    const float4* __restrict__ img_f4 =
        reinterpret_cast<const float4*>(mask) + (size_t)img * IMG_F4;

    int xmin = INT_MAX, ymin = INT_MAX;
    int xmax = 0,       ymax = 0;

    const int base = chunk * (THREADS * F4_PER_THREAD);

    // Explicit x2 load batching: both loads issue before either is consumed.
    // With unroll 2 the compiler can keep ~4 LDG.128 in flight per thread.
#pragma unroll 2
    for (int k = 0; k < F4_PER_THREAD; k += 2) {
        const int i0 = base + k * THREADS + tid;
        const int i1 = i0 + THREADS;
        const float4 v0 = img_f4[i0];
        const float4 v1 = img_f4[i1];
        process_f4(v0, i0, xmin, ymin, xmax, ymax);
        process_f4(v1, i1, xmin, ymin, xmax, ymax);
    }

    // Warp reduce (redux.sync)
    xmin = __reduce_min_sync(0xFFFFFFFFu, xmin);
    xmax = __reduce_max_sync(0xFFFFFFFFu, xmax);
    ymin = __reduce_min_sync(0xFFFFFFFFu, ymin);
    ymax = __reduce_max_sync(0xFFFFFFFFu, ymax);

    __shared__ int s_xmin[8], s_xmax[8], s_ymin[8], s_ymax[8];
    const int wid = tid >> 5;
    const int lid = tid & 31;
    if (lid == 0) {
        s_xmin[wid] = xmin; s_xmax[wid] = xmax;
        s_ymin[wid] = ymin; s_ymax[wid] = ymax;
    }
    __syncthreads();

    __shared__ bool s_is_last;
    if (tid == 0) {
        int bxmin = s_xmin[0], bxmax = s_xmax[0];
        int bymin = s_ymin[0], bymax = s_ymax[0];
#pragma unroll
        for (int w = 1; w < 8; w++) {
            bxmin = min(bxmin, s_xmin[w]); bxmax = max(bxmax, s_xmax[w]);
            bymin = min(bymin, s_ymin[w]); bymax = max(bymax, s_ymax[w]);
        }
        g_part[img * CHUNKS + chunk] = make_int4(bxmin, bymin, bxmax, bymax);
        __threadfence();
        const unsigned int ticket = atomicAdd(&g_counter, 1u);
        s_is_last = (ticket == GRID_BLOCKS - 1);
    }
    __syncthreads();

    if (!s_is_last) return;

    // ---- Last block: final reduce of 1024 partials + write outputs ----
    // Thread i handles image i (256 threads, 256 images).
    {
        const int i = tid;
        int fxmin = INT_MAX, fymin = INT_MAX, fxmax = 0, fymax = 0;
#pragma unroll
        for (int cch = 0; cch < CHUNKS; cch++) {
            const int4 p = __ldcg(&g_part[i * CHUNKS + cch]);
            fxmin = min(fxmin, p.x); fymin = min(fymin, p.y);
            fxmax = max(fxmax, p.z); fymax = max(fymax, p.w);
        }

        const float xminf = (float)fxmin;
        const float yminf = (float)fymin;
        const float xmaxf = (float)fxmax;
        const float ymaxf = (float)fymax;

        // Output layout (concatenated flattened tuple, all float32):
        //   [0,   256)  object_found           [B, C, 1]
        //   [256, 1280) bounding_boxes_scaled  [B, C, 4]  (x_min,y_min,x_max,y_max)
        //   [1280,2304) bounding_boxes         [B, C, 4]  (scaled * 2)
        out[i] = ((ymaxf > yminf) && (xmaxf > xminf)) ? 1.0f : 0.0f;

        float* bb = out + 256 + i * 4;
        bb[0] = xminf; bb[1] = yminf; bb[2] = xmaxf; bb[3] = ymaxf;

        float* bb2 = out + 1280 + i * 4;
        bb2[0] = xminf * 2.0f; bb2[1] = yminf * 2.0f;
        bb2[2] = xmaxf * 2.0f; bb2[3] = ymaxf * 2.0f;

        // Reset ticket counter for the next graph replay.
        if (tid == 0) g_counter = 0u;
    }
}

extern "C" void kernel_launch(void* const* d_in, const int* in_sizes, int n_in,
                              void* d_out, int out_size) {
    const float* mask = (const float*)d_in[0];
    float* out = (float*)d_out;

    dim3 grid(CHUNKS, N_IMG);
    bb_fused_kernel<<<grid, THREADS>>>(mask, out);
}

// round 5
// speedup vs baseline: 1.0726x; 1.0041x over previous
#include <cuda_runtime.h>
#include <cuda_bf16.h>
#include <limits.h>

#define B_DIM 32
#define C_DIM 8
#define H_DIM 512
#define W_DIM 512
#define N_IMG (B_DIM * C_DIM)            // 256
#define IMG_ELEMS (H_DIM * W_DIM)        // 262144
#define IMG_F4 (IMG_ELEMS / 4)           // 65536 float4 per image
#define TILES_PER_IMG 16                 // tile = 4096 float4 = 64 KB
#define N_TILES (N_IMG * TILES_PER_IMG)  // 4096
#define TILE_F4 (IMG_F4 / TILES_PER_IMG) // 4096
#define THREADS 256
#define F4_PER_THREAD (TILE_F4 / THREADS) // 16
#define GRID_BLOCKS (148 * 6)             // 888: one full wave at 6 blocks/SM

// Per-tile partials {xmin, ymin, xmax, ymax}; fully overwritten each launch.
__device__ int4 g_part[N_TILES];
// Work-stealing ticket + completion counter. Static-init 0; last block resets
// both so graph replays are deterministic.
__device__ unsigned int g_tile_ctr = 0;
__device__ unsigned int g_done_ctr = 0;

__device__ __forceinline__ void process_f4(const float4 v, const int idx,
                                           int& xmin, int& ymin,
                                           int& xmax, int& ymax) {
    const int h1 = (idx >> 7) + 1;              // row + 1 (128 f4 per row)
    const int w0 = ((idx & 127) << 2) + 1;      // col of lane 0, +1

    const bool a = v.x >= 0.5f;
    const bool b = v.y >= 0.5f;
    const bool c = v.z >= 0.5f;
    const bool d = v.w >= 0.5f;
    const bool any = a | b | c | d;
    const bool all = a & b & c & d;

    // y: all 4 lanes share the row. min = all?h1:0, max = any?h1:0
    ymin = min(ymin, all ? h1 : 0);
    ymax = max(ymax, any ? h1 : 0);
    // x: lanes are w0..w0+3. min = all?w0:0; max = any?(w0+highest set):0
    const int hi = d ? 3 : (c ? 2 : (b ? 1 : 0));
    xmin = min(xmin, all ? w0 : 0);
    xmax = max(xmax, any ? (w0 + hi) : 0);
}

__global__ __launch_bounds__(THREADS, 6) void bb_fused_kernel(
    const float* __restrict__ mask, float* __restrict__ out) {
    const int tid = threadIdx.x;
    const int wid = tid >> 5;
    const int lid = tid & 31;

    __shared__ int s_xmin[8], s_xmax[8], s_ymin[8], s_ymax[8];
    __shared__ unsigned int s_tile;
    __shared__ bool s_is_last;

    const float4* __restrict__ mask_f4 = reinterpret_cast<const float4*>(mask);

    for (;;) {
        if (tid == 0) s_tile = atomicAdd(&g_tile_ctr, 1u);
        __syncthreads();
        const unsigned int tile = s_tile;
        if (tile >= N_TILES) break;

        const int img   = tile >> 4;           // tile / TILES_PER_IMG
        const int chunk = tile & 15;
        // f4 index of tile start within the image
        const int tile_base = chunk * TILE_F4;
        const float4* __restrict__ img_f4 = mask_f4 + (size_t)img * IMG_F4;

        int xmin = INT_MAX, ymin = INT_MAX;
        int xmax = 0,       ymax = 0;

        // 4-deep explicit load batching: all 4 LDG.128 issue before any use.
#pragma unroll
        for (int k = 0; k < F4_PER_THREAD; k += 4) {
            const int i0 = tile_base + k * THREADS + tid;
            const int i1 = i0 + THREADS;
            const int i2 = i0 + 2 * THREADS;
            const int i3 = i0 + 3 * THREADS;
            const float4 v0 = img_f4[i0];
            const float4 v1 = img_f4[i1];
            const float4 v2 = img_f4[i2];
            const float4 v3 = img_f4[i3];
            process_f4(v0, i0, xmin, ymin, xmax, ymax);
            process_f4(v1, i1, xmin, ymin, xmax, ymax);
            process_f4(v2, i2, xmin, ymin, xmax, ymax);
            process_f4(v3, i3, xmin, ymin, xmax, ymax);
        }

        // Block reduce for this tile
        xmin = __reduce_min_sync(0xFFFFFFFFu, xmin);
        xmax = __reduce_max_sync(0xFFFFFFFFu, xmax);
        ymin = __reduce_min_sync(0xFFFFFFFFu, ymin);
        ymax = __reduce_max_sync(0xFFFFFFFFu, ymax);
        if (lid == 0) {
            s_xmin[wid] = xmin; s_xmax[wid] = xmax;
            s_ymin[wid] = ymin; s_ymax[wid] = ymax;
        }
        __syncthreads();
        if (tid == 0) {
            int bxmin = s_xmin[0], bxmax = s_xmax[0];
            int bymin = s_ymin[0], bymax = s_ymax[0];
#pragma unroll
            for (int w = 1; w < 8; w++) {
                bxmin = min(bxmin, s_xmin[w]); bxmax = max(bxmax, s_xmax[w]);
                bymin = min(bymin, s_ymin[w]); bymax = max(bymax, s_ymax[w]);
            }
            g_part[tile] = make_int4(bxmin, bymin, bxmax, bymax);
        }
        __syncthreads();   // protect s_* and s_tile before next iteration
    }

    // Completion ticket: last block does the final reduce + output.
    if (tid == 0) {
        __threadfence();
        const unsigned int ticket = atomicAdd(&g_done_ctr, 1u);
        s_is_last = (ticket == GRID_BLOCKS - 1);
    }
    __syncthreads();
    if (!s_is_last) return;

    // ---- Last block: reduce 4096 partials, write 2304 outputs ----
    {
        const int i = tid;  // one image per thread
        int fxmin = INT_MAX, fymin = INT_MAX, fxmax = 0, fymax = 0;
#pragma unroll
        for (int c = 0; c < TILES_PER_IMG; c++) {
            const int4 p = __ldcg(&g_part[i * TILES_PER_IMG + c]);
            fxmin = min(fxmin, p.x); fymin = min(fymin, p.y);
            fxmax = max(fxmax, p.z); fymax = max(fymax, p.w);
        }

        const float xminf = (float)fxmin;
        const float yminf = (float)fymin;
        const float xmaxf = (float)fxmax;
        const float ymaxf = (float)fymax;

        // Layout: [0,256) object_found | [256,1280) bbox_scaled | [1280,2304) bbox*2
        out[i] = ((ymaxf > yminf) && (xmaxf > xminf)) ? 1.0f : 0.0f;

        float* bb = out + 256 + i * 4;
        bb[0] = xminf; bb[1] = yminf; bb[2] = xmaxf; bb[3] = ymaxf;

        float* bb2 = out + 1280 + i * 4;
        bb2[0] = xminf * 2.0f; bb2[1] = yminf * 2.0f;
        bb2[2] = xmaxf * 2.0f; bb2[3] = ymaxf * 2.0f;

        // Reset counters for the next graph replay.
        if (tid == 0) { g_tile_ctr = 0u; g_done_ctr = 0u; }
    }
}

extern "C" void kernel_launch(void* const* d_in, const int* in_sizes, int n_in,
                              void* d_out, int out_size) {
    const float* mask = (const float*)d_in[0];
    float* out = (float*)d_out;
    bb_fused_kernel<<<GRID_BLOCKS, THREADS>>>(mask, out);
}